// round 6
// baseline (speedup 1.0000x reference)
#include <cuda_runtime.h>
#include <math.h>

#define B_   8192
#define F_   32
#define P_   512
#define H_   256
#define BM   16        // rows per CTA in K2
#define KC   16        // K-chunk for W1 staging in K2
#define NT   256

#define PITCH2 257     // pitch (in float2) for paired-W1 smem chunk

// K2 smem (floats): xt 16*512 + sW2 8*257*2 + red 16*8
#define SMEM2_FLOATS (BM * P_ + (KC / 2) * PITCH2 * 2 + BM * 8)

// 16 MB scratch for the normalized mix, + work-stealing counter
__device__ float        g_xn[B_ * P_];
__device__ unsigned int g_ctr;

// packed fp32x2 FMA
__device__ __forceinline__ void ffma2(double& acc, double x, double w) {
    asm("fma.rn.f32x2 %0, %1, %2, %0;"
        : "+l"(*reinterpret_cast<unsigned long long*>(&acc))
        : "l"(*reinterpret_cast<unsigned long long*>(&x)),
          "l"(*reinterpret_cast<unsigned long long*>(&w)));
}

__global__ void k_init() { g_ctr = 0u; }

// ---------------- K1: ragged weighted mix + LayerNorm, warp-per-row stealing ----
__global__ __launch_bounds__(256, 4)
void k_mix_ln(const float* __restrict__ phys,
              const float* __restrict__ ratios,
              const int*   __restrict__ lengths,
              const float* __restrict__ ln_gamma,
              const float* __restrict__ ln_beta)
{
    const int lane = threadIdx.x & 31;

    for (;;) {
        unsigned task = 0;
        if (lane == 0) task = atomicAdd(&g_ctr, 1u);
        task = __shfl_sync(0xffffffffu, task, 0);
        if (task >= (unsigned)B_) break;
        const int b   = (int)task;
        const int len = lengths[b];

        // normalized weights: lane f holds wn_f (0 for f >= len)
        float rv = ratios[b * F_ + lane];
        float rm = (lane < len) ? rv : 0.0f;
        float S = rm;
        #pragma unroll
        for (int o = 16; o > 0; o >>= 1) S += __shfl_xor_sync(0xffffffffu, S, o);
        const float wn = rm / (S + 1e-8f);

        // accumulate: lane owns float4 slots lane, lane+32, lane+64, lane+96
        float4 a0 = {0,0,0,0}, a1 = {0,0,0,0}, a2 = {0,0,0,0}, a3 = {0,0,0,0};
        const float4* pb = (const float4*)(phys + (size_t)b * (F_ * P_));
        const int len2 = (len + 1) & ~1;            // pad to even; wn padded lane = 0
        for (int f = 0; f < len2; f += 2) {
            const float w0 = __shfl_sync(0xffffffffu, wn, f);
            const float w1 = __shfl_sync(0xffffffffu, wn, f + 1);
            const float4* p0 = pb + f * (P_ / 4) + lane;
            const float4* p1 = p0 + (P_ / 4);
            float4 u0 = p0[0],  u1 = p0[32], u2 = p0[64], u3 = p0[96];
            float4 v0 = p1[0],  v1 = p1[32], v2 = p1[64], v3 = p1[96];
            a0.x += w0*u0.x + w1*v0.x; a0.y += w0*u0.y + w1*v0.y;
            a0.z += w0*u0.z + w1*v0.z; a0.w += w0*u0.w + w1*v0.w;
            a1.x += w0*u1.x + w1*v1.x; a1.y += w0*u1.y + w1*v1.y;
            a1.z += w0*u1.z + w1*v1.z; a1.w += w0*u1.w + w1*v1.w;
            a2.x += w0*u2.x + w1*v2.x; a2.y += w0*u2.y + w1*v2.y;
            a2.z += w0*u2.z + w1*v2.z; a2.w += w0*u2.w + w1*v2.w;
            a3.x += w0*u3.x + w1*v3.x; a3.y += w0*u3.y + w1*v3.y;
            a3.z += w0*u3.z + w1*v3.z; a3.w += w0*u3.w + w1*v3.w;
        }

        // LayerNorm stats
        float s  = a0.x+a0.y+a0.z+a0.w + a1.x+a1.y+a1.z+a1.w
                 + a2.x+a2.y+a2.z+a2.w + a3.x+a3.y+a3.z+a3.w;
        float s2 = a0.x*a0.x+a0.y*a0.y+a0.z*a0.z+a0.w*a0.w
                 + a1.x*a1.x+a1.y*a1.y+a1.z*a1.z+a1.w*a1.w
                 + a2.x*a2.x+a2.y*a2.y+a2.z*a2.z+a2.w*a2.w
                 + a3.x*a3.x+a3.y*a3.y+a3.z*a3.z+a3.w*a3.w;
        #pragma unroll
        for (int o = 16; o > 0; o >>= 1) {
            s  += __shfl_xor_sync(0xffffffffu, s,  o);
            s2 += __shfl_xor_sync(0xffffffffu, s2, o);
        }
        const float mu   = s * (1.0f / P_);
        const float var  = fmaxf(s2 * (1.0f / P_) - mu * mu, 0.0f);
        const float rstd = rsqrtf(var + 1e-5f);

        float4* xr = (float4*)(g_xn + (size_t)b * P_);
        float4 av[4] = {a0, a1, a2, a3};
        #pragma unroll
        for (int i = 0; i < 4; i++) {
            const int vi = lane + 32 * i;
            float4 g  = ((const float4*)ln_gamma)[vi];
            float4 be = ((const float4*)ln_beta)[vi];
            float4 o4;
            o4.x = (av[i].x - mu) * rstd * g.x + be.x;
            o4.y = (av[i].y - mu) * rstd * g.y + be.y;
            o4.z = (av[i].z - mu) * rstd * g.z + be.z;
            o4.w = (av[i].w - mu) * rstd * g.w + be.w;
            xr[vi] = o4;
        }
    }
}

// ---------------- K2: xn @ W1^T (FFMA2) + ReLU + W2 dot + nan_to_num ----------
__global__ __launch_bounds__(NT, 4)
void k_head(const float* __restrict__ W1,
            const float* __restrict__ b1,
            const float* __restrict__ W2,
            const float* __restrict__ b2,
            float*       __restrict__ out)
{
    extern __shared__ float sm[];
    float*  xt  = sm;                                   // [BM][P_]
    float2* sW2 = (float2*)(sm + BM * P_);              // [KC/2][PITCH2]
    float*  red = sm + BM * P_ + (KC / 2) * PITCH2 * 2; // [BM][8]

    const int tid  = threadIdx.x;
    const int wid  = tid >> 5;
    const int lane = tid & 31;
    const int b0   = blockIdx.x * BM;

    // stage x tile (coalesced float4, L2-resident after K1)
    {
        const float4* src = (const float4*)(g_xn + (size_t)b0 * P_);
        float4* dst = (float4*)xt;
        #pragma unroll
        for (int i = 0; i < (BM * P_ / 4) / NT; i++)   // 8 iters
            dst[tid + i * NT] = src[tid + i * NT];
    }
    __syncthreads();

    double hacc2[BM];
    #pragma unroll
    for (int r = 0; r < BM; r++) hacc2[r] = 0.0;

    for (int kk = 0; kk < P_; kk += KC) {
        // stage W1[:, kk:kk+KC] as k-pairs: sW2[kp][j]
        #pragma unroll
        for (int t = 0; t < (H_ * KC) / (NT * 4); t++) {   // 4 iters
            const int e = 4 * (tid + t * NT);
            const int j = e >> 4;                // 0..255
            const int k = e & 15;                // multiple of 4
            float4 v = *(const float4*)(W1 + j * P_ + kk + k);
            float2* dst = sW2 + (k >> 1) * PITCH2 + j;
            dst[0]      = make_float2(v.x, v.y);
            dst[PITCH2] = make_float2(v.z, v.w);
        }
        __syncthreads();

        double wreg[KC / 2];
        #pragma unroll
        for (int kp = 0; kp < KC / 2; kp++)
            wreg[kp] = *(const double*)(sW2 + kp * PITCH2 + tid);

        #pragma unroll
        for (int r = 0; r < BM; r++) {
            const double2* xr = (const double2*)(xt + r * P_ + kk);
            #pragma unroll
            for (int q = 0; q < KC / 4; q++) {   // 4 x LDS.128 broadcast
                double2 v = xr[q];
                ffma2(hacc2[r], v.x, wreg[2 * q]);
                ffma2(hacc2[r], v.y, wreg[2 * q + 1]);
            }
        }
        __syncthreads();
    }

    // epilogue
    const float w2  = W2[tid];
    const float bb1 = b1[tid];
    #pragma unroll
    for (int r = 0; r < BM; r++) {
        float2 p = *reinterpret_cast<float2*>(&hacc2[r]);
        float h = p.x + p.y + bb1;
        h = fmaxf(h, 0.0f);
        float v = h * w2;
        #pragma unroll
        for (int o = 16; o > 0; o >>= 1) v += __shfl_xor_sync(0xffffffffu, v, o);
        if (lane == 0) red[r * 8 + wid] = v;
    }
    __syncthreads();

    if (tid < BM) {
        float y = b2[0];
        #pragma unroll
        for (int w = 0; w < 8; w++) y += red[tid * 8 + w];
        if (isnan(y)) y = 0.0f;
        else if (isinf(y)) y = (y > 0.0f) ? 3.4028234663852886e38f : -3.4028234663852886e38f;
        out[b0 + tid] = y;
    }
}

extern "C" void kernel_launch(void* const* d_in, const int* in_sizes, int n_in,
                              void* d_out, int out_size)
{
    const float* phys     = (const float*)d_in[0];
    const float* ratios   = (const float*)d_in[1];
    const int*   lengths  = (const int*)  d_in[2];
    const float* ln_gamma = (const float*)d_in[3];
    const float* ln_beta  = (const float*)d_in[4];
    const float* W1       = (const float*)d_in[5];
    const float* b1       = (const float*)d_in[6];
    const float* W2       = (const float*)d_in[7];
    const float* b2       = (const float*)d_in[8];
    float* out = (float*)d_out;

    const int smem2 = SMEM2_FLOATS * (int)sizeof(float);
    cudaFuncSetAttribute(k_head, cudaFuncAttributeMaxDynamicSharedMemorySize, smem2);

    k_init<<<1, 1>>>();
    k_mix_ln<<<148 * 4, 256>>>(phys, ratios, lengths, ln_gamma, ln_beta);
    k_head<<<B_ / BM, NT, smem2>>>(W1, b1, W2, b2, out);
}